// round 14
// baseline (speedup 1.0000x reference)
#include <cuda_runtime.h>

// Problem constants
#define B_   16
#define OUT_ 1024
#define IN_  2048

__global__ __launch_bounds__(256)
void led_kernel(const int*   __restrict__ x,       // (B,1,IN) int32
                const float* __restrict__ weight,  // (OUT,IN)
                const float* __restrict__ trace,   // (B,OUT,IN)
                const float* __restrict__ delay,   // (B,OUT,IN)
                const float* __restrict__ dinit,   // constant tensor; only [0] read
                const float* __restrict__ dt_p,
                const float* __restrict__ tau_p,
                const float* __restrict__ alpha_p,
                float* __restrict__ pot,           // (B,OUT) — written once per row
                float* __restrict__ folded)        // (B,OUT,IN) flat
{
    // Barrier-free block reduction state. Init before any memory latency;
    // the single __syncthreads here is nearly free (all warps arrive together).
    __shared__ float    ssum;
    __shared__ unsigned scnt;
    if (threadIdx.x == 0) { ssum = 0.0f; scnt = 0u; }
    __syncthreads();

    const int row = blockIdx.x;          // b*OUT + o
    const int b   = row >> 10;           // / OUT_
    const int o   = row & (OUT_ - 1);

    const float k     = __ldg(dt_p) / __ldg(tau_p);
    const float alpha = __ldg(alpha_p);
    const float d0    = __ldg(dinit);    // constant-valued tensor
    const float c1    = 1.0f - k;        // t_new = c1*t + (k*alpha)*x
    const float c0    = k * alpha;

    const long base = (long)row * IN_;
    const float4* __restrict__ tr4 = (const float4*)(trace  + base);
    const float4* __restrict__ dl4 = (const float4*)(delay  + base);
    const float4* __restrict__ w4  = (const float4*)(weight + (long)o * IN_);
    const int4*   __restrict__ x4  = (const int4*)  (x      + (long)b * IN_);
    float4* __restrict__ out4 = (float4*)(folded + base);

    const int j0 = threadIdx.x;
    const int j1 = threadIdx.x + 256;

    // Front-batch all loads (MLP). Streaming reads: last-use (L1 no-retain).
    // weight/x: default policy (L1-cacheable; weight rows revisit the same SM).
    float4 t0 = __ldlu(tr4 + j0);
    float4 t1 = __ldlu(tr4 + j1);
    float4 dA = __ldlu(dl4 + j0);
    float4 dB = __ldlu(dl4 + j1);
    float4 w0 = __ldg (w4  + j0);
    float4 w1 = __ldg (w4  + j1);
    int4   xA = __ldg (x4  + j0);
    int4   xB = __ldg (x4  + j1);

    float acc = 0.0f;

    // ---- iter 0 ----
    {
        float xf0 = (float)xA.x, xf1 = (float)xA.y, xf2 = (float)xA.z, xf3 = (float)xA.w;

        t0.x = fmaf(c1, t0.x, c0 * xf0);
        t0.y = fmaf(c1, t0.y, c0 * xf1);
        t0.z = fmaf(c1, t0.z, c0 * xf2);
        t0.w = fmaf(c1, t0.w, c0 * xf3);
        __stcs(out4 + j0, t0);

        // spike ⇔ delay == 1 - d0*x   (exact integer-valued floats)
        if (dA.x == fmaf(-d0, xf0, 1.0f)) acc += w0.x;
        if (dA.y == fmaf(-d0, xf1, 1.0f)) acc += w0.y;
        if (dA.z == fmaf(-d0, xf2, 1.0f)) acc += w0.z;
        if (dA.w == fmaf(-d0, xf3, 1.0f)) acc += w0.w;
    }
    // ---- iter 1 ----
    {
        float xf0 = (float)xB.x, xf1 = (float)xB.y, xf2 = (float)xB.z, xf3 = (float)xB.w;

        t1.x = fmaf(c1, t1.x, c0 * xf0);
        t1.y = fmaf(c1, t1.y, c0 * xf1);
        t1.z = fmaf(c1, t1.z, c0 * xf2);
        t1.w = fmaf(c1, t1.w, c0 * xf3);
        __stcs(out4 + j1, t1);

        if (dB.x == fmaf(-d0, xf0, 1.0f)) acc += w1.x;
        if (dB.y == fmaf(-d0, xf1, 1.0f)) acc += w1.y;
        if (dB.z == fmaf(-d0, xf2, 1.0f)) acc += w1.z;
        if (dB.w == fmaf(-d0, xf3, 1.0f)) acc += w1.w;
    }

    // Warp reduce (5 shuffles).
    #pragma unroll
    for (int off = 16; off > 0; off >>= 1)
        acc += __shfl_xor_sync(0xFFFFFFFFu, acc, off);

    // Barrier-free cross-warp combine: smem atomic + arrival counter.
    // The 8th (last) arriving warp leader sees all prior ssum adds
    // (fence orders ssum-add before scnt-add per thread) and stores pot.
    if ((threadIdx.x & 31) == 0) {
        atomicAdd(&ssum, acc);
        __threadfence_block();
        unsigned prev = atomicAdd(&scnt, 1u);
        if (prev == 7u) {
            __threadfence_block();
            pot[row] = ssum;
        }
    }
}

extern "C" void kernel_launch(void* const* d_in, const int* in_sizes, int n_in,
                              void* d_out, int out_size) {
    const int*   x      = (const int*)  d_in[0];
    const float* weight = (const float*)d_in[1];
    const float* trace  = (const float*)d_in[2];
    const float* delay  = (const float*)d_in[3];
    const float* dinit  = (const float*)d_in[4];
    const float* dt_p   = (const float*)d_in[5];
    const float* tau_p  = (const float*)d_in[6];
    const float* alpha_p= (const float*)d_in[7];

    float* pot    = (float*)d_out;                 // (B,1,OUT) = 16384 floats
    float* folded = pot + (long)B_ * OUT_;         // (B,IN,OUT) flat = trace_new flat

    // Max L1 carveout: block uses 8B smem; give the full unified cache to L1D
    // so weight rows revisiting the same SM hit in L1. Host-side, deterministic,
    // capture-safe (no stream work enqueued).
    cudaFuncSetAttribute(led_kernel,
                         cudaFuncAttributePreferredSharedMemoryCarveout,
                         cudaSharedmemCarveoutMaxL1);

    led_kernel<<<B_ * OUT_, 256>>>(x, weight, trace, delay, dinit,
                                   dt_p, tau_p, alpha_p, pot, folded);
}

// round 15
// speedup vs baseline: 1.0124x; 1.0124x over previous
#include <cuda_runtime.h>

// Problem constants
#define B_   16
#define OUT_ 1024
#define IN_  2048

__global__ __launch_bounds__(256)
void led_kernel(const int*   __restrict__ x,       // (B,1,IN) int32
                const float* __restrict__ weight,  // (OUT,IN)
                const float* __restrict__ trace,   // (B,OUT,IN)
                const float* __restrict__ delay,   // (B,OUT,IN)
                const float* __restrict__ dinit,   // constant tensor; only [0] read
                const float* __restrict__ dt_p,
                const float* __restrict__ tau_p,
                const float* __restrict__ alpha_p,
                float* __restrict__ pot,           // (B,OUT) — written once per row
                float* __restrict__ folded)        // (B,OUT,IN) flat
{
    // Barrier-free block reduction state. Init before any memory latency;
    // the single __syncthreads here is nearly free (all warps arrive together).
    __shared__ float    ssum;
    __shared__ unsigned scnt;
    if (threadIdx.x == 0) { ssum = 0.0f; scnt = 0u; }
    __syncthreads();

    const int row = blockIdx.x;          // b*OUT + o
    const int b   = row >> 10;           // / OUT_
    const int o   = row & (OUT_ - 1);

    const float k     = __ldg(dt_p) / __ldg(tau_p);
    const float alpha = __ldg(alpha_p);
    const float d0    = __ldg(dinit);    // constant-valued tensor
    const float c1    = 1.0f - k;        // t_new = c1*t + (k*alpha)*x
    const float c0    = k * alpha;

    const long base = (long)row * IN_;
    const float4* __restrict__ tr4 = (const float4*)(trace  + base);
    const float4* __restrict__ dl4 = (const float4*)(delay  + base);
    const float4* __restrict__ w4  = (const float4*)(weight + (long)o * IN_);
    const int4*   __restrict__ x4  = (const int4*)  (x      + (long)b * IN_);
    float4* __restrict__ out4 = (float4*)(folded + base);

    const int j0 = threadIdx.x;
    const int j1 = threadIdx.x + 256;

    // Front-batch all loads (MLP). Streaming tensors use evict-first.
    float4 t0 = __ldcs(tr4 + j0);
    float4 t1 = __ldcs(tr4 + j1);
    float4 dA = __ldcs(dl4 + j0);
    float4 dB = __ldcs(dl4 + j1);
    float4 w0 = __ldg (w4  + j0);
    float4 w1 = __ldg (w4  + j1);
    int4   xA = __ldg (x4  + j0);
    int4   xB = __ldg (x4  + j1);

    float acc = 0.0f;

    // ---- iter 0 ----
    {
        float xf0 = (float)xA.x, xf1 = (float)xA.y, xf2 = (float)xA.z, xf3 = (float)xA.w;

        t0.x = fmaf(c1, t0.x, c0 * xf0);
        t0.y = fmaf(c1, t0.y, c0 * xf1);
        t0.z = fmaf(c1, t0.z, c0 * xf2);
        t0.w = fmaf(c1, t0.w, c0 * xf3);
        __stcs(out4 + j0, t0);

        // spike ⇔ delay == 1 - d0*x   (exact integer-valued floats)
        if (dA.x == fmaf(-d0, xf0, 1.0f)) acc += w0.x;
        if (dA.y == fmaf(-d0, xf1, 1.0f)) acc += w0.y;
        if (dA.z == fmaf(-d0, xf2, 1.0f)) acc += w0.z;
        if (dA.w == fmaf(-d0, xf3, 1.0f)) acc += w0.w;
    }
    // ---- iter 1 ----
    {
        float xf0 = (float)xB.x, xf1 = (float)xB.y, xf2 = (float)xB.z, xf3 = (float)xB.w;

        t1.x = fmaf(c1, t1.x, c0 * xf0);
        t1.y = fmaf(c1, t1.y, c0 * xf1);
        t1.z = fmaf(c1, t1.z, c0 * xf2);
        t1.w = fmaf(c1, t1.w, c0 * xf3);
        __stcs(out4 + j1, t1);

        if (dB.x == fmaf(-d0, xf0, 1.0f)) acc += w1.x;
        if (dB.y == fmaf(-d0, xf1, 1.0f)) acc += w1.y;
        if (dB.z == fmaf(-d0, xf2, 1.0f)) acc += w1.z;
        if (dB.w == fmaf(-d0, xf3, 1.0f)) acc += w1.w;
    }

    // Warp reduce (5 shuffles).
    #pragma unroll
    for (int off = 16; off > 0; off >>= 1)
        acc += __shfl_xor_sync(0xFFFFFFFFu, acc, off);

    // Barrier-free cross-warp combine: smem atomic + arrival counter.
    // The 8th (last) arriving warp leader sees all prior ssum adds
    // (fence orders ssum-add before scnt-add per thread) and stores pot.
    if ((threadIdx.x & 31) == 0) {
        atomicAdd(&ssum, acc);
        __threadfence_block();
        unsigned prev = atomicAdd(&scnt, 1u);
        if (prev == 7u) {
            __threadfence_block();
            pot[row] = ssum;
        }
    }
}

extern "C" void kernel_launch(void* const* d_in, const int* in_sizes, int n_in,
                              void* d_out, int out_size) {
    const int*   x      = (const int*)  d_in[0];
    const float* weight = (const float*)d_in[1];
    const float* trace  = (const float*)d_in[2];
    const float* delay  = (const float*)d_in[3];
    const float* dinit  = (const float*)d_in[4];
    const float* dt_p   = (const float*)d_in[5];
    const float* tau_p  = (const float*)d_in[6];
    const float* alpha_p= (const float*)d_in[7];

    float* pot    = (float*)d_out;                 // (B,1,OUT) = 16384 floats
    float* folded = pot + (long)B_ * OUT_;         // (B,IN,OUT) flat = trace_new flat

    led_kernel<<<B_ * OUT_, 256>>>(x, weight, trace, delay, dinit,
                                   dt_p, tau_p, alpha_p, pot, folded);
}